// round 1
// baseline (speedup 1.0000x reference)
#include <cuda_runtime.h>

// Problem constants (fixed by the dataset): B=2, N=64, CI=32, CO=32
#define B2 2
#define NP 64
#define CIc 32
#define COc 32

// Scratch (no device mallocs allowed) — ~64 KB total
__device__ float g_fs[B2][NP][CIc];   // sum over d
__device__ float g_fd[B2][NP][CIc];   // sum over c
__device__ float g_Ua[B2][NP][COc];   // per-a term (+const folded in)
__device__ float g_Ub[B2][NP][COc];   // per-b term

// ---------------------------------------------------------------------------
// Kernel 1: feature reductions fs[z,c,j] = sum_d f, fd[z,d,j] = sum_c f
// grid = 256 blocks (128 fs rows + 128 fd cols), 256 threads
// ---------------------------------------------------------------------------
__global__ void pc_reduce_kernel(const float* __restrict__ f) {
    int idx   = blockIdx.x;
    int which = idx >> 7;          // 0 -> fs, 1 -> fd
    int z     = (idx >> 6) & 1;
    int p     = idx & 63;
    int j     = threadIdx.x & 31;
    int w     = threadIdx.x >> 5;  // 0..7

    float acc = 0.f;
    if (which == 0) {
        // fs: fixed c = p, sum over d (contiguous rows of 32 floats)
        const float* base = f + (size_t)((z * NP + p) * NP) * CIc + j;
        #pragma unroll
        for (int d = w; d < NP; d += 8) acc += base[d * CIc];
    } else {
        // fd: fixed d = p, sum over c (stride N*CI)
        const float* base = f + (size_t)(z * NP * NP + p) * CIc + j;
        #pragma unroll
        for (int c = w; c < NP; c += 8) acc += base[(size_t)c * NP * CIc];
    }

    __shared__ float sh[8][32];
    sh[w][j] = acc;
    __syncthreads();
    if (w == 0) {
        float s = 0.f;
        #pragma unroll
        for (int k = 0; k < 8; k++) s += sh[k][j];
        if (which == 0) g_fs[z][p][j] = s;
        else            g_fd[z][p][j] = s;
    }
}

// ---------------------------------------------------------------------------
// Kernel 2: per-z tiny contractions -> Ua, Ub
// grid = 2 (one block per z), 256 threads
// ---------------------------------------------------------------------------
__global__ void pc_prep_kernel(const float* __restrict__ geom,
                               const float* __restrict__ W,
                               const void*  __restrict__ nnp) {
    int z   = blockIdx.x;
    int tid = threadIdx.x;

    __shared__ float gsh[NP][3];
    __shared__ float GFs[3][CIc];
    __shared__ float GFd[3][CIc];
    __shared__ float fts[CIc];
    __shared__ float Aa[3][COc];
    __shared__ float Ab[3][COc];
    __shared__ float Cs[3][COc];
    __shared__ float constv[COc];

    // n_norm: tolerate int32 or float32 encoding
    int   iv = *(const int*)nnp;
    float nn = (iv >= 1 && iv <= (1 << 20)) ? (float)iv : *(const float*)nnp;
    float s  = rsqrtf(6.0f * nn * nn);

    for (int t = tid; t < NP * 3; t += blockDim.x)
        gsh[t / 3][t % 3] = geom[z * NP * 3 + t];
    __syncthreads();

    // GFs[x][j] = sum_c g[c][x]*fs[c][j]; GFd likewise; fts[j] = sum_c fs[c][j]
    if (tid < 96) {
        int x = tid >> 5, j = tid & 31;
        float acc = 0.f;
        #pragma unroll 4
        for (int c = 0; c < NP; c++) acc += gsh[c][x] * g_fs[z][c][j];
        GFs[x][j] = acc;
    } else if (tid < 192) {
        int t = tid - 96;
        int x = t >> 5, j = t & 31;
        float acc = 0.f;
        #pragma unroll 4
        for (int d = 0; d < NP; d++) acc += gsh[d][x] * g_fd[z][d][j];
        GFd[x][j] = acc;
    } else if (tid < 224) {
        int j = tid - 192;
        float acc = 0.f;
        #pragma unroll 4
        for (int c = 0; c < NP; c++) acc += g_fs[z][c][j];
        fts[j] = acc;
    }
    __syncthreads();

    // Per (x,i): A-combos over ft, and the constant-term contraction
    if (tid < 96) {
        int x = tid >> 5, i = tid & 31;
        const float* Wx = W + (size_t)x * (6 * COc * CIc) + i * CIc;
        float aa = 0.f, ab = 0.f, cc = 0.f;
        #pragma unroll
        for (int j = 0; j < CIc; j++) {
            float w1 = Wx[0 * COc * CIc + j];
            float w2 = Wx[1 * COc * CIc + j];
            float w3 = Wx[2 * COc * CIc + j];
            float w4 = Wx[3 * COc * CIc + j];
            float w5 = Wx[4 * COc * CIc + j];
            float w6 = Wx[5 * COc * CIc + j];
            float fj = fts[j];
            aa += (w1 + w2 + w3) * fj;            // Ua direction (terms 1,2,3)
            ab += (w1 - w4 - w5) * fj;            // Ub direction (terms 1,4,5)
            float gsv = GFs[x][j], gdv = GFd[x][j];
            cc += (w2 + w4) * gsv + (w3 + w5) * gdv + w6 * (gdv - gsv);
        }
        Aa[x][i] = aa; Ab[x][i] = ab; Cs[x][i] = cc;
    }
    __syncthreads();

    if (tid < COc)
        constv[tid] = s * (Cs[0][tid] + Cs[1][tid] + Cs[2][tid]);
    __syncthreads();

    // Ua[a][i] = const[i] - s * <g_a, Aa[:,i]>;  Ub[b][i] = s * <g_b, Ab[:,i]>
    for (int t = tid; t < NP * COc; t += blockDim.x) {
        int a = t >> 5, i = t & 31;
        float g0 = gsh[a][0], g1 = gsh[a][1], g2 = gsh[a][2];
        g_Ua[z][a][i] = constv[i] - s * (g0 * Aa[0][i] + g1 * Aa[1][i] + g2 * Aa[2][i]);
        g_Ub[z][a][i] =            s * (g0 * Ab[0][i] + g1 * Ab[1][i] + g2 * Ab[2][i]);
    }
}

// ---------------------------------------------------------------------------
// Kernel 3: out[z,a,b,i] = Ua[z,a,i] + Ub[z,b,i]
// grid = 128 blocks (z,a), 256 threads
// ---------------------------------------------------------------------------
__global__ void pc_out_kernel(float* __restrict__ out) {
    int z   = blockIdx.x >> 6;
    int a   = blockIdx.x & 63;
    int tid = threadIdx.x;

    __shared__ float ua[COc];
    if (tid < COc) ua[tid] = g_Ua[z][a][tid];
    __syncthreads();

    int i  = tid & 31;
    int b0 = tid >> 5;
    float uai = ua[i];
    float* o = out + (size_t)((z * NP + a) * NP) * COc;
    #pragma unroll
    for (int b = b0; b < NP; b += 8)
        o[b * COc + i] = uai + g_Ub[z][b][i];
}

// ---------------------------------------------------------------------------
extern "C" void kernel_launch(void* const* d_in, const int* in_sizes, int n_in,
                              void* d_out, int out_size) {
    const float* features = (const float*)d_in[0]; // [2,64,64,32]
    const float* geometry = (const float*)d_in[1]; // [2,64,3]
    const float* W        = (const float*)d_in[2]; // [3,6144]
    const void*  n_norm   = d_in[3];               // scalar
    float* out = (float*)d_out;                    // [2,64,64,32]

    pc_reduce_kernel<<<256, 256>>>(features);
    pc_prep_kernel<<<2, 256>>>(geometry, W, n_norm);
    pc_out_kernel<<<128, 256>>>(out);
}

// round 2
// speedup vs baseline: 2.1429x; 2.1429x over previous
#include <cuda_runtime.h>

// Problem constants (fixed by the dataset): B=2, N=64, CI=32, CO=32
#define B2 2
#define NP 64
#define CIc 32
#define COc 32
#define K1_BLKS_PER_Z 32
#define ROWS_PER_BLK (NP * NP / K1_BLKS_PER_Z)   // 128

// Scratch: per-block partial sums of the 7 weighted feature reductions
// [z][block][t][j], t: 0=ft, 1..3=GFs(x), 4..6=GFd(x)
__device__ float g_part[B2][K1_BLKS_PER_Z][7][CIc];

// ---------------------------------------------------------------------------
// K1: streaming weighted reduction over features.
// Row r = c*64 + d. Weights per row: {1, g[c].xyz, g[d].xyz}.
// grid = 64 (2 z * 32), block = 256 (8 warps * 32 lanes; lane = channel j)
// ---------------------------------------------------------------------------
__global__ void pc_k1(const float* __restrict__ f,
                      const float* __restrict__ geom) {
    int z   = blockIdx.x >> 5;
    int blk = blockIdx.x & 31;
    int j   = threadIdx.x & 31;
    int w   = threadIdx.x >> 5;

    __shared__ float gsh[NP][3];
    for (int t = threadIdx.x; t < NP * 3; t += 256)
        gsh[t / 3][t % 3] = geom[z * NP * 3 + t];
    __syncthreads();

    int r0 = blk * ROWS_PER_BLK;
    const float* base = f + ((size_t)z * NP * NP + r0) * CIc + j;

    float a0 = 0.f, a1 = 0.f, a2 = 0.f, a3 = 0.f, a4 = 0.f, a5 = 0.f, a6 = 0.f;
    #pragma unroll
    for (int k = 0; k < ROWS_PER_BLK / 8; k++) {
        int rr = w + 8 * k;            // 0..127
        float v = base[rr * CIc];      // coalesced: lanes j consecutive
        int r = r0 + rr;
        int c = r >> 6, d = r & 63;
        a0 += v;
        a1 += v * gsh[c][0];
        a2 += v * gsh[c][1];
        a3 += v * gsh[c][2];
        a4 += v * gsh[d][0];
        a5 += v * gsh[d][1];
        a6 += v * gsh[d][2];
    }

    __shared__ float sh[8][7][CIc];
    sh[w][0][j] = a0; sh[w][1][j] = a1; sh[w][2][j] = a2; sh[w][3][j] = a3;
    sh[w][4][j] = a4; sh[w][5][j] = a5; sh[w][6][j] = a6;
    __syncthreads();

    if (threadIdx.x < 224) {
        int t  = threadIdx.x >> 5;     // 0..6
        int jj = threadIdx.x & 31;
        float s = 0.f;
        #pragma unroll
        for (int k = 0; k < 8; k++) s += sh[k][t][jj];
        g_part[z][blk][t][jj] = s;
    }
}

// ---------------------------------------------------------------------------
// K2: one block per (z, a). Re-reduce partials (L2), tiny W contractions,
// then write out[z,a,b,i] = Ua[a,i] + s*<g_b, Ab[:,i]>.
// grid = 128, block = 256
// ---------------------------------------------------------------------------
__global__ void pc_k2(const float* __restrict__ geom,
                      const float* __restrict__ W,
                      const void*  __restrict__ nnp,
                      float* __restrict__ out) {
    int z    = blockIdx.x >> 6;
    int a    = blockIdx.x & 63;
    int tid  = threadIdx.x;
    int lane = tid & 31;
    int w    = tid >> 5;

    __shared__ float gsh[NP][3];
    __shared__ float red[7][CIc];          // ft, GFs[3], GFd[3]
    __shared__ float Aa[3][COc], Ab[3][COc], Cst[3][COc];
    __shared__ float UaS[COc];

    for (int t = tid; t < NP * 3; t += 256)
        gsh[t / 3][t % 3] = geom[z * NP * 3 + t];

    if (tid < 224) {
        int t  = tid >> 5;                 // 0..6
        int jj = tid & 31;
        float acc = 0.f;
        #pragma unroll
        for (int p = 0; p < K1_BLKS_PER_Z; p++)
            acc += g_part[z][p][t][jj];    // coalesced lanes, independent loads
        red[t][jj] = acc;
    }
    __syncthreads();

    // Per (x,i) pair: warp-cooperative over j (lane = j, coalesced W loads)
    for (int p = w; p < 96; p += 8) {
        int x = p >> 5, i = p & 31;
        const float* Wb = W + (size_t)x * (6 * COc * CIc) + i * CIc + lane;
        float w1 = Wb[0 * COc * CIc];
        float w2 = Wb[1 * COc * CIc];
        float w3 = Wb[2 * COc * CIc];
        float w4 = Wb[3 * COc * CIc];
        float w5 = Wb[4 * COc * CIc];
        float w6 = Wb[5 * COc * CIc];
        float ftl = red[0][lane];
        float gs  = red[1 + x][lane];
        float gd  = red[4 + x][lane];
        float aa = (w1 + w2 + w3) * ftl;                       // Ua direction
        float ab = (w1 - w4 - w5) * ftl;                       // Ub direction
        float cc = (w2 + w4) * gs + (w3 + w5) * gd + w6 * (gd - gs);
        #pragma unroll
        for (int o = 16; o; o >>= 1) {
            aa += __shfl_xor_sync(0xFFFFFFFFu, aa, o);
            ab += __shfl_xor_sync(0xFFFFFFFFu, ab, o);
            cc += __shfl_xor_sync(0xFFFFFFFFu, cc, o);
        }
        if (lane == 0) { Aa[x][i] = aa; Ab[x][i] = ab; Cst[x][i] = cc; }
    }
    __syncthreads();

    // n_norm: tolerate int32 or float32 encoding
    int   iv = *(const int*)nnp;
    float nn = (iv >= 1 && iv <= (1 << 20)) ? (float)iv : *(const float*)nnp;
    float s  = rsqrtf(6.0f * nn * nn);

    if (tid < COc) {
        float cv = s * (Cst[0][tid] + Cst[1][tid] + Cst[2][tid]);
        float g0 = gsh[a][0], g1 = gsh[a][1], g2 = gsh[a][2];
        UaS[tid] = cv - s * (g0 * Aa[0][tid] + g1 * Aa[1][tid] + g2 * Aa[2][tid]);
        Ab[0][tid] *= s; Ab[1][tid] *= s; Ab[2][tid] *= s;   // pre-scale
    }
    __syncthreads();

    float ua  = UaS[lane];
    float ab0 = Ab[0][lane], ab1 = Ab[1][lane], ab2 = Ab[2][lane];
    float* o = out + ((size_t)(z * NP + a) * NP) * COc + lane;
    #pragma unroll
    for (int b = w; b < NP; b += 8)
        o[b * COc] = ua + gsh[b][0] * ab0 + gsh[b][1] * ab1 + gsh[b][2] * ab2;
}

// ---------------------------------------------------------------------------
extern "C" void kernel_launch(void* const* d_in, const int* in_sizes, int n_in,
                              void* d_out, int out_size) {
    const float* features = (const float*)d_in[0]; // [2,64,64,32]
    const float* geometry = (const float*)d_in[1]; // [2,64,3]
    const float* W        = (const float*)d_in[2]; // [3,6144]
    const void*  n_norm   = d_in[3];               // scalar
    float* out = (float*)d_out;                    // [2,64,64,32]

    pc_k1<<<B2 * K1_BLKS_PER_Z, 256>>>(features, geometry);
    pc_k2<<<B2 * NP, 256>>>(geometry, W, n_norm, out);
}

// round 3
// speedup vs baseline: 2.2266x; 1.0391x over previous
#include <cuda_runtime.h>

// Problem constants (fixed by the dataset): B=2, N=64, CI=32, CO=32
#define B2 2
#define NP 64
#define CIc 32
#define COc 32
#define K1_BLKS_PER_Z 32
#define ROWS_PER_BLK (NP * NP / K1_BLKS_PER_Z)   // 128

// Scratch: per-block partial sums of the 7 weighted feature reductions
// [z][block][t][j], t: 0=ft, 1..3=GFs(x), 4..6=GFd(x)
__device__ float g_part[B2][K1_BLKS_PER_Z][7][CIc];

// ---------------------------------------------------------------------------
// K1: streaming weighted reduction over features.
// Row r = c*64 + d. Weights per row: {1, g[c].xyz, g[d].xyz}.
// grid = 64 (2 z * 32), block = 256 (8 warps * 32 lanes; lane = channel j)
// ---------------------------------------------------------------------------
__global__ void pc_k1(const float* __restrict__ f,
                      const float* __restrict__ geom) {
    int z   = blockIdx.x >> 5;
    int blk = blockIdx.x & 31;
    int j   = threadIdx.x & 31;
    int w   = threadIdx.x >> 5;

    __shared__ float gsh[NP][3];
    for (int t = threadIdx.x; t < NP * 3; t += 256)
        gsh[t / 3][t % 3] = geom[z * NP * 3 + t];
    __syncthreads();

    int r0 = blk * ROWS_PER_BLK;
    const float* base = f + ((size_t)z * NP * NP + r0) * CIc + j;

    float a0 = 0.f, a1 = 0.f, a2 = 0.f, a3 = 0.f, a4 = 0.f, a5 = 0.f, a6 = 0.f;
    #pragma unroll
    for (int k = 0; k < ROWS_PER_BLK / 8; k++) {
        int rr = w + 8 * k;            // 0..127
        float v = base[rr * CIc];      // coalesced: lanes j consecutive
        int r = r0 + rr;
        int c = r >> 6, d = r & 63;
        a0 += v;
        a1 += v * gsh[c][0];
        a2 += v * gsh[c][1];
        a3 += v * gsh[c][2];
        a4 += v * gsh[d][0];
        a5 += v * gsh[d][1];
        a6 += v * gsh[d][2];
    }

    __shared__ float sh[8][7][CIc];
    sh[w][0][j] = a0; sh[w][1][j] = a1; sh[w][2][j] = a2; sh[w][3][j] = a3;
    sh[w][4][j] = a4; sh[w][5][j] = a5; sh[w][6][j] = a6;
    __syncthreads();

    if (threadIdx.x < 224) {
        int t  = threadIdx.x >> 5;     // 0..6
        int jj = threadIdx.x & 31;
        float s = 0.f;
        #pragma unroll
        for (int k = 0; k < 8; k++) s += sh[k][t][jj];
        g_part[z][blk][t][jj] = s;
    }
}

// ---------------------------------------------------------------------------
// K2: one block per (z, a). Re-reduce partials (L2), tiny W contractions,
// then write out[z,a,b,i] = Ua[a,i] + s*<g_b, Ab[:,i]>.
// grid = 128, block = 256
// ---------------------------------------------------------------------------
__global__ void pc_k2(const float* __restrict__ geom,
                      const float* __restrict__ W,
                      const void*  __restrict__ nnp,
                      float* __restrict__ out) {
    int z    = blockIdx.x >> 6;
    int a    = blockIdx.x & 63;
    int tid  = threadIdx.x;
    int lane = tid & 31;
    int w    = tid >> 5;

    __shared__ float gsh[NP][3];
    __shared__ float red[7][CIc];          // ft, GFs[3], GFd[3]
    __shared__ float Aa[3][COc], Ab[3][COc], Cst[3][COc];
    __shared__ float UaS[COc];

    for (int t = tid; t < NP * 3; t += 256)
        gsh[t / 3][t % 3] = geom[z * NP * 3 + t];

    if (tid < 224) {
        int t  = tid >> 5;                 // 0..6
        int jj = tid & 31;
        float acc = 0.f;
        #pragma unroll
        for (int p = 0; p < K1_BLKS_PER_Z; p++)
            acc += g_part[z][p][t][jj];    // coalesced lanes, independent loads
        red[t][jj] = acc;
    }
    __syncthreads();

    // Per (x,i) pair: warp-cooperative over j (lane = j, coalesced W loads)
    for (int p = w; p < 96; p += 8) {
        int x = p >> 5, i = p & 31;
        const float* Wb = W + (size_t)x * (6 * COc * CIc) + i * CIc + lane;
        float w1 = Wb[0 * COc * CIc];
        float w2 = Wb[1 * COc * CIc];
        float w3 = Wb[2 * COc * CIc];
        float w4 = Wb[3 * COc * CIc];
        float w5 = Wb[4 * COc * CIc];
        float w6 = Wb[5 * COc * CIc];
        float ftl = red[0][lane];
        float gs  = red[1 + x][lane];
        float gd  = red[4 + x][lane];
        float aa = (w1 + w2 + w3) * ftl;                       // Ua direction
        float ab = (w1 - w4 - w5) * ftl;                       // Ub direction
        float cc = (w2 + w4) * gs + (w3 + w5) * gd + w6 * (gd - gs);
        #pragma unroll
        for (int o = 16; o; o >>= 1) {
            aa += __shfl_xor_sync(0xFFFFFFFFu, aa, o);
            ab += __shfl_xor_sync(0xFFFFFFFFu, ab, o);
            cc += __shfl_xor_sync(0xFFFFFFFFu, cc, o);
        }
        if (lane == 0) { Aa[x][i] = aa; Ab[x][i] = ab; Cst[x][i] = cc; }
    }
    __syncthreads();

    // n_norm: tolerate int32 or float32 encoding
    int   iv = *(const int*)nnp;
    float nn = (iv >= 1 && iv <= (1 << 20)) ? (float)iv : *(const float*)nnp;
    float s  = rsqrtf(6.0f * nn * nn);

    if (tid < COc) {
        float cv = s * (Cst[0][tid] + Cst[1][tid] + Cst[2][tid]);
        float g0 = gsh[a][0], g1 = gsh[a][1], g2 = gsh[a][2];
        UaS[tid] = cv - s * (g0 * Aa[0][tid] + g1 * Aa[1][tid] + g2 * Aa[2][tid]);
        Ab[0][tid] *= s; Ab[1][tid] *= s; Ab[2][tid] *= s;   // pre-scale
    }
    __syncthreads();

    float ua  = UaS[lane];
    float ab0 = Ab[0][lane], ab1 = Ab[1][lane], ab2 = Ab[2][lane];
    float* o = out + ((size_t)(z * NP + a) * NP) * COc + lane;
    #pragma unroll
    for (int b = w; b < NP; b += 8)
        o[b * COc] = ua + gsh[b][0] * ab0 + gsh[b][1] * ab1 + gsh[b][2] * ab2;
}

// ---------------------------------------------------------------------------
extern "C" void kernel_launch(void* const* d_in, const int* in_sizes, int n_in,
                              void* d_out, int out_size) {
    const float* features = (const float*)d_in[0]; // [2,64,64,32]
    const float* geometry = (const float*)d_in[1]; // [2,64,3]
    const float* W        = (const float*)d_in[2]; // [3,6144]
    const void*  n_norm   = d_in[3];               // scalar
    float* out = (float*)d_out;                    // [2,64,64,32]

    pc_k1<<<B2 * K1_BLKS_PER_Z, 256>>>(features, geometry);
    pc_k2<<<B2 * NP, 256>>>(geometry, W, n_norm, out);
}